// round 14
// baseline (speedup 1.0000x reference)
#include <cuda_runtime.h>

#define TB 32
#define TT 50
#define TS 49
#define DD 100
#define NBR 6
#define SPQ 4
#define RK 10

// ---------------- device scratch ----------------
__device__ __align__(16) float g_eagg[2][TB][TS][DD];
__device__ __align__(16) float g_gates[TB][TS][4 * DD];
__device__ __align__(16) float g_h[TB][TS][DD];
__device__ __align__(16) float g_vq[DD], g_vk[DD];
__device__ __align__(16) float g_resp[2][DD];
__device__ __align__(16) float g_w1t[10000];   // W1^T : [k*100+d]
__device__ __align__(16) float g_w2t[10000];   // W2^T
__device__ __align__(16) float g_wfT[10000];   // W_fusion(:,0:100)^T : [k*100+d]
__device__ __align__(16) float g_wihT[40000];  // W_ih^T : [k*400+j]
__device__ float g_cq, g_ck;

#define FMA4(ac, a, w) { ac.x += (a) * (w).x; ac.y += (a) * (w).y; ac.z += (a) * (w).z; ac.w += (a) * (w).w; }

__device__ __forceinline__ float tanha(float x) {
    float y;
    asm("tanh.approx.f32 %0, %1;" : "=f"(y) : "f"(x));
    return y;
}

// ---------------- A: precompute + transpose (grid 12) ----------------
__global__ void setup_kernel(const float* __restrict__ W_query,
                             const float* __restrict__ b_query,
                             const float* __restrict__ W_key,
                             const float* __restrict__ b_key,
                             const float* __restrict__ W_w,
                             const float* __restrict__ emb_r,
                             const float* __restrict__ W_fusion,
                             const float* __restrict__ b_fusion,
                             const float* __restrict__ agg_w,
                             const float* __restrict__ W_ih) {
    int blk = blockIdx.x, tid = threadIdx.x;
    if (blk == 0) {
        for (int k = tid; k < DD; k += 256) {
            float a = 0.f;
            for (int d = 0; d < DD; d++) a += W_query[d * DD + k] * W_w[d];
            g_vq[k] = a;
        }
        if (tid == 0) {
            float c = 0.f;
            for (int d = 0; d < DD; d++) c += b_query[d] * W_w[d];
            g_cq = c;
        }
    } else if (blk == 1) {
        for (int k = tid; k < DD; k += 256) {
            float a = 0.f;
            for (int d = 0; d < DD; d++) a += W_key[d * DD + k] * W_w[DD + d];
            g_vk[k] = a;
        }
        if (tid == 0) {
            float c = 0.f;
            for (int d = 0; d < DD; d++) c += b_key[d] * W_w[DD + d];
            g_ck = c;
        }
    } else if (blk <= 3) {
        int r = blk - 2;
        for (int d = tid; d < DD; d += 256) {
            float a = b_fusion[d];
            for (int k = 0; k < DD; k++)
                a += emb_r[r * DD + k] * W_fusion[d * 2 * DD + DD + k];
            g_resp[r][d] = a;
        }
    } else if (blk == 4) {
        for (int i = tid; i < 10000; i += 256) {
            int d = i / 100, k = i % 100;
            g_w1t[k * 100 + d] = agg_w[10000 + i];
        }
    } else if (blk == 5) {
        for (int i = tid; i < 10000; i += 256) {
            int d = i / 100, k = i % 100;
            g_w2t[k * 100 + d] = agg_w[20000 + i];
        }
    } else if (blk == 6) {
        for (int i = tid; i < 10000; i += 256) {
            int d = i / 100, k = i % 100;
            g_wfT[k * 100 + d] = W_fusion[d * 200 + k];
        }
    } else {  // blk 7..11: W_ih 40000 elems, 8000 each
        int base = (blk - 7) * 8000;
        for (int i = base + tid; i < base + 8000; i += 256) {
            int j = i / 100, k = i - j * 100;
            g_wihT[k * 400 + j] = W_ih[i];
        }
    }
}

// warp-cooperative 100x100 matvec (weights from global, coalesced rows)
__device__ __forceinline__ void mv100(const float* __restrict__ in,
                                      const float* __restrict__ Wg,
                                      const float* __restrict__ bg,
                                      float* out, int tid) {
    int w = tid >> 5, l = tid & 31;
    for (int d = w; d < 100; d += 8) {
        float p = 0.f;
        for (int k = l; k < 100; k += 32) p += in[k] * Wg[d * 100 + k];
        for (int o = 16; o > 0; o >>= 1) p += __shfl_xor_sync(0xffffffffu, p, o);
        if (l == 0) out[d] = tanha(p + bg[d]);
    }
}

// 6x100 matmul, 2x2 reg tiles (float2 weights), 150 threads
__device__ __forceinline__ void mm6(const float* __restrict__ in,
                                    const float* __restrict__ W1T,
                                    const float* __restrict__ b1g,
                                    float* out, int tid) {
    if (tid < 150) {
        int r0 = (tid / 50) * 2, d0 = (tid % 50) * 2;
        float a00 = 0.f, a01 = 0.f, a10 = 0.f, a11 = 0.f;
#pragma unroll 4
        for (int k = 0; k < 100; k++) {
            float2 w = *(const float2*)&W1T[k * 100 + d0];
            float x0 = in[r0 * 100 + k], x1 = in[r0 * 100 + 100 + k];
            a00 += x0 * w.x; a01 += x0 * w.y;
            a10 += x1 * w.x; a11 += x1 * w.y;
        }
        float b0 = b1g[d0], b1 = b1g[d0 + 1];
        out[r0 * 100 + d0] = tanha(a00 + b0);
        out[r0 * 100 + d0 + 1] = tanha(a01 + b1);
        out[r0 * 100 + 100 + d0] = tanha(a10 + b0);
        out[r0 * 100 + 100 + d0 + 1] = tanha(a11 + b1);
    }
}

// ---------------- B: graph aggregation ----------------
__global__ __launch_bounds__(256, 6) void agg_kernel(
    const int* __restrict__ user, const int* __restrict__ question,
    const int* __restrict__ mask,
    const int* __restrict__ q_nb, const int* __restrict__ s_nb,
    const int* __restrict__ u_nb, const int* __restrict__ q_nb2,
    const float* __restrict__ emb_q, const float* __restrict__ emb_q2,
    const float* __restrict__ emb_s, const float* __restrict__ emb_u,
    const float* __restrict__ agg_w, const float* __restrict__ agg_b,
    const float* __restrict__ W_last, const float* __restrict__ b_last) {
    int t = blockIdx.x, b = blockIdx.y, side = blockIdx.z, tid = threadIdx.x;
    int qt = question[b * TT + t];
    float* outg = &g_eagg[side][b][t][0];
    if (mask[b * TT + t] == 0) {
        const float* src = side ? emb_q2 + (size_t)qt * DD : emb_q + (size_t)qt * DD;
        for (int d = tid; d < DD; d += 256) outg[d] = src[d];
        return;
    }
    extern __shared__ float sm[];
    float* e2s = sm;            // 3600
    float* e1  = e2s + 3600;    // 600
    float* e1b = e1 + 600;      // 600
    float* s6  = e1b + 600;     // 600
    float* e0v = s6 + 600;      // 100
    float* e0b = e0v + 100;     // 100
    float* e0c = e0b + 100;     // 100
    float* s1  = e0c + 100;     // 100  -> 5800 floats
    int* sn1 = (int*)(s1 + 100);  // 8
    int* sn2 = sn1 + 8;           // 36
    int* sn3 = sn2 + 36;          // 216 -> 260 ints

    int n0 = side ? user[b * TT + t] : qt;
    const int* tA = side ? u_nb : q_nb;
    const int* tB = side ? q_nb2 : s_nb;
    const float* eE = side ? emb_u : emb_q;
    const float* eO = side ? emb_q2 : emb_s;
    const float* b0g = agg_b;
    const float* b1g = agg_b + DD;
    const float* b2g = agg_b + 2 * DD;
    const float* W0g = agg_w;

    int g0 = tid / 100;
    int d0i = tid - g0 * 100;

    if (tid < NBR) sn1[tid] = tA[n0 * NBR + tid];
    for (int d = tid; d < 100; d += 256) e0v[d] = eE[(size_t)n0 * DD + d];
    __syncthreads();
    if (tid < 36) sn2[tid] = tB[sn1[tid / 6] * NBR + tid % 6];
    for (int i = tid; i < 600; i += 256)
        e1[i] = eO[(size_t)sn1[i / 100] * DD + i % 100];
    __syncthreads();
    if (tid < 216) sn3[tid] = tA[sn2[tid / 6] * NBR + tid % 6];
    {
        int g = g0, d = d0i;
        for (int i = tid; i < 3600; i += 256) {
            e2s[i] = eE[(size_t)sn2[g] * DD + d];
            d += 56; g += 2;
            if (d >= 100) { d -= 100; ++g; }
        }
    }
    __syncthreads();
    for (int i = tid; i < 600; i += 256) {
        int r = i / 100, d = i % 100;
        float s = 0.f;
        for (int r2 = 0; r2 < 6; r2++) s += e2s[(r * 6 + r2) * 100 + d];
        s6[i] = s * (1.f / 6.f) + e1[i];
    }
    if (tid < 100) {
        float s = 0.f;
        for (int r = 0; r < 6; r++) s += e1[r * 100 + tid];
        s1[tid] = s * (1.f / 6.f) + e0v[tid];
    }
    __syncthreads();
    mv100(s1, W0g, b0g, e0b, tid);  // i=0 j=0
    {
        int g = g0, d = d0i;
        for (int i = tid; i < 3600; i += 256) {
            const int* s3 = sn3 + g * 6;
            float s = eO[(size_t)s3[0] * DD + d] + eO[(size_t)s3[1] * DD + d] +
                      eO[(size_t)s3[2] * DD + d] + eO[(size_t)s3[3] * DD + d] +
                      eO[(size_t)s3[4] * DD + d] + eO[(size_t)s3[5] * DD + d];
            e2s[i] += s * (1.f / 6.f);
            d += 56; g += 2;
            if (d >= 100) { d -= 100; ++g; }
        }
    }
    __syncthreads();
    // i=0 j=2 : 36x100 @ W2^T, 4x4 reg tiles, in-place
    float4 ac0, ac1, ac2, ac3;
    int r0 = 0, c0 = 0;
    if (tid < 225) {
        r0 = (tid / 25) * 4; c0 = (tid % 25) * 4;
        ac0 = make_float4(0, 0, 0, 0); ac1 = ac0; ac2 = ac0; ac3 = ac0;
#pragma unroll 2
        for (int k = 0; k < 100; k++) {
            float4 w = *(const float4*)&g_w2t[k * 100 + c0];
            float x0 = e2s[r0 * 100 + k];
            float x1 = e2s[r0 * 100 + 100 + k];
            float x2 = e2s[r0 * 100 + 200 + k];
            float x3 = e2s[r0 * 100 + 300 + k];
            FMA4(ac0, x0, w); FMA4(ac1, x1, w); FMA4(ac2, x2, w); FMA4(ac3, x3, w);
        }
    }
    __syncthreads();
    if (tid < 225) {
        float bb0 = b2g[c0], bb1 = b2g[c0 + 1], bb2 = b2g[c0 + 2], bb3 = b2g[c0 + 3];
        float* o0 = e2s + r0 * 100 + c0;
        o0[0] = tanha(ac0.x + bb0); o0[1] = tanha(ac0.y + bb1); o0[2] = tanha(ac0.z + bb2); o0[3] = tanha(ac0.w + bb3);
        o0[100] = tanha(ac1.x + bb0); o0[101] = tanha(ac1.y + bb1); o0[102] = tanha(ac1.z + bb2); o0[103] = tanha(ac1.w + bb3);
        o0[200] = tanha(ac2.x + bb0); o0[201] = tanha(ac2.y + bb1); o0[202] = tanha(ac2.z + bb2); o0[203] = tanha(ac2.w + bb3);
        o0[300] = tanha(ac3.x + bb0); o0[301] = tanha(ac3.y + bb1); o0[302] = tanha(ac3.z + bb2); o0[303] = tanha(ac3.w + bb3);
    }
    mm6(s6, g_w1t, b1g, e1b, tid);  // i=0 j=1
    __syncthreads();
    for (int i = tid; i < 600; i += 256) {
        int r = i / 100, d = i % 100;
        float s = 0.f;
        for (int r2 = 0; r2 < 6; r2++) s += e2s[(r * 6 + r2) * 100 + d];
        s6[i] = s * (1.f / 6.f) + e1b[i];
    }
    if (tid < 100) {
        float s = 0.f;
        for (int r = 0; r < 6; r++) s += e1b[r * 100 + tid];
        s1[tid] = s * (1.f / 6.f) + e0b[tid];
    }
    __syncthreads();
    mv100(s1, W0g, b0g, e0c, tid);  // i=1 j=0
    mm6(s6, g_w1t, b1g, e1, tid);   // i=1 j=1
    __syncthreads();
    if (tid < 100) {
        float s = 0.f;
        for (int r = 0; r < 6; r++) s += e1[r * 100 + tid];
        s1[tid] = s * (1.f / 6.f) + e0c[tid];
    }
    __syncthreads();
    mv100(s1, W0g, b0g, e0v, tid);  // i=2 j=0
    __syncthreads();
    mv100(e0v, W_last, b_last, outg, tid);  // final
}

// ---------------- C: fused fusion + input gates ----------------
__global__ __launch_bounds__(256) void fusion_gates_kernel(
    const int* __restrict__ response, const float* __restrict__ w1p,
    const float* __restrict__ w2p, const float* __restrict__ b_ih,
    const float* __restrict__ b_hh) {
    int tc = blockIdx.x, b = blockIdx.y, tid = threadIdx.x;
    int t0 = tc * 4;
    __shared__ float eh[400], et[400];
    float w1 = *w1p, w2 = *w2p;
    for (int i = tid; i < 400; i += 256) {
        int t = t0 + i / 100, d = i % 100;
        eh[i] = (t < TS) ? w1 * g_eagg[0][b][t][d] + w2 * g_eagg[1][b][t][d] : 0.f;
    }
    __syncthreads();
    if (tid < 100) {
        int tt = tid / 25, d0 = (tid % 25) * 4;
        int t = t0 + tt;
        if (t < TS) {
            float4 ac = make_float4(0, 0, 0, 0);
            const float* x = eh + tt * 100;
#pragma unroll 4
            for (int k = 0; k < 100; k++) {
                float4 w = *(const float4*)&g_wfT[k * 100 + d0];
                FMA4(ac, x[k], w);
            }
            int r = response[b * TT + t];
            et[tt * 100 + d0]     = fmaxf(ac.x + g_resp[r][d0], 0.f);
            et[tt * 100 + d0 + 1] = fmaxf(ac.y + g_resp[r][d0 + 1], 0.f);
            et[tt * 100 + d0 + 2] = fmaxf(ac.z + g_resp[r][d0 + 2], 0.f);
            et[tt * 100 + d0 + 3] = fmaxf(ac.w + g_resp[r][d0 + 3], 0.f);
        }
    }
    __syncthreads();
    for (int u = tid; u < 400; u += 256) {
        int tt = u / 100, j0 = (u % 100) * 4;
        int t = t0 + tt;
        if (t < TS) {
            float4 ac = make_float4(0, 0, 0, 0);
            const float* x = et + tt * 100;
#pragma unroll 4
            for (int k = 0; k < 100; k++) {
                float4 w = *(const float4*)&g_wihT[k * 400 + j0];
                FMA4(ac, x[k], w);
            }
            g_gates[b][t][j0]     = ac.x + b_ih[j0] + b_hh[j0];
            g_gates[b][t][j0 + 1] = ac.y + b_ih[j0 + 1] + b_hh[j0 + 1];
            g_gates[b][t][j0 + 2] = ac.z + b_ih[j0 + 2] + b_hh[j0 + 2];
            g_gates[b][t][j0 + 3] = ac.w + b_ih[j0 + 3] + b_hh[j0 + 3];
        }
    }
}

// ---------------- D: LSTM scan — W_hh split across thread pairs (no spills) ----------------
__global__ __launch_bounds__(800, 1) void scan_kernel(
    const int* __restrict__ mask, const float* __restrict__ W_hh,
    float* __restrict__ out) {
    int b = blockIdx.x, tid = threadIdx.x;
    __shared__ __align__(16) float h[100];
    __shared__ float c[100], gs[400];
    __shared__ int mlist[TS + 1];
    __shared__ int snm;
    int j = tid >> 1, half = tid & 1;   // thread pair (2j, 2j+1) owns row j
    float w[50];
    {
        const float* wr = W_hh + j * 100 + half * 50;
#pragma unroll
        for (int k = 0; k < 50; k += 2) {
            float2 v = *(const float2*)&wr[k];
            w[k] = v.x; w[k + 1] = v.y;
        }
    }
    if (tid < 100) { h[tid] = 0.f; c[tid] = 0.f; }
    if (tid == 0) {
        out[b * TT] = 0.5f;
        int n = 0;
        for (int t = 0; t < TS; t++)
            if (mask[b * TT + t]) mlist[n++] = t;
        mlist[n] = TS;
        snm = n;
    }
    __syncthreads();
    int nm = snm;
    int first = (nm > 0) ? mlist[0] : TS;
    if (tid < 100)
        for (int t = 0; t < first; t++) g_h[b][t][tid] = 0.f;
    float ginc = (nm > 0 && half == 0) ? g_gates[b][mlist[0]][j] : 0.f;
    const float* hh = h + half * 50;
    for (int idx = 0; idx < nm; idx++) {
        int tm = mlist[idx], tn = mlist[idx + 1];
        {
            float a0 = 0.f, a1 = 0.f;
#pragma unroll
            for (int k = 0; k < 48; k += 4) {   // k = 0,4,...,44 covers hh[0..47]
                float2 h0 = *(const float2*)&hh[k];
                float2 h1 = *(const float2*)&hh[k + 2];
                a0 += h0.x * w[k]     + h0.y * w[k + 1];
                a1 += h1.x * w[k + 2] + h1.y * w[k + 3];
            }
            float2 ht = *(const float2*)&hh[48];   // tail 48,49
            a0 += ht.x * w[48] + ht.y * w[49];
            float p = a0 + a1;
            p += __shfl_xor_sync(0xffffffffu, p, 1);   // pair combine
            if (half == 0) gs[j] = p + ginc;
        }
        // prefetch next step's input-gate element (even lanes only)
        if (idx + 1 < nm && half == 0) ginc = g_gates[b][mlist[idx + 1]][j];
        __syncthreads();
        if (tid < 100) {
            float gi = gs[tid], gf = gs[100 + tid], gg = gs[200 + tid], go = gs[300 + tid];
            float si = 1.f / (1.f + expf(-gi));
            float sf = 1.f / (1.f + expf(-gf));
            float so = 1.f / (1.f + expf(-go));
            float c2 = sf * c[tid] + si * tanhf(gg);
            float h2 = so * tanhf(c2);
            h[tid] = h2; c[tid] = c2;
            for (int t = tm; t < tn; t++) g_h[b][t][tid] = h2;
        }
        __syncthreads();
    }
}

// ---------------- E: prep + attention fused, grid (TS, TB) ----------------
__global__ __launch_bounds__(128) void attn_kernel(
    const int* __restrict__ question, const int* __restrict__ qs_index,
    const float* __restrict__ emb_q, const float* __restrict__ emb_s,
    const float* __restrict__ b_w, float* __restrict__ out) {
    int t = blockIdx.x, b = blockIdx.y, tid = threadIdx.x;
    __shared__ float st[1100], qsm[500], vks[100], sc[52], lbuf[64], gbuf[64],
                     klb[16], red[2], sql[5];
    __shared__ int sidx[10], ssv[10];
    int qn = question[b * TT + t + 1];
    for (int i = tid; i < 500; i += 128) {
        int q = i / 100, d = i % 100;
        qsm[i] = (q == 0) ? emb_q[(size_t)qn * DD + d]
                          : emb_s[(size_t)qs_index[qn * SPQ + q - 1] * DD + d];
    }
    for (int d = tid; d < 100; d += 128) vks[d] = g_vk[d];
    __syncthreads();
    if (tid < 5) {
        float a = g_cq;
        for (int d = 0; d < 100; d++) a += qsm[tid * 100 + d] * g_vq[d];
        sql[tid] = a;
    }
    for (int i = tid; i < t; i += 128) {
        const float* er = emb_q + (size_t)question[b * TT + i] * DD;
        float a = 0.f;
#pragma unroll 4
        for (int d = 0; d < 100; d++) a += er[d] * qsm[d];
        sc[i] = a;
    }
    __syncthreads();
    if (tid == 0) {  // exact stable top-k over i < t
        unsigned long long used = 0ULL;
        for (int s = 0; s < RK; s++) {
            float best = -1e38f; int bi = -1;
            for (int i = 0; i < t; i++)
                if (!((used >> i) & 1ULL) && sc[i] > best) { best = sc[i]; bi = i; }
            if (bi >= 0) { sidx[s] = bi; ssv[s] = 1; used |= 1ULL << bi; }
            else         { sidx[s] = 0;  ssv[s] = 0; }
        }
    }
    __syncthreads();
    for (int i = tid; i < 1100; i += 128) {
        int s = i / 100, d = i % 100;
        int row = (s == 0) ? t : sidx[s - 1];
        st[i] = g_h[b][row][d];
    }
    __syncthreads();
    float ckb = g_ck + b_w[0];
    if (tid < 55) {
        int q = tid / 11, s = tid % 11;
        bool v = (s == 0) || ssv[s - 1];
        float a = 0.f;
        if (v) {
            const float* qr = qsm + q * 100;
            const float* sr = st + s * 100;
#pragma unroll 4
            for (int d = 0; d < 100; d++) a += qr[d] * sr[d];
        }
        gbuf[tid] = a;
    } else if (tid < 66) {
        int s = tid - 55;
        bool v = (s == 0) || ssv[s - 1];
        float a = -1e30f;
        if (v) {
            a = ckb;
            const float* sr = st + s * 100;
#pragma unroll 4
            for (int d = 0; d < 100; d++) a += sr[d] * vks[d];
        }
        klb[s] = a;
    }
    __syncthreads();
    if (tid < 64) lbuf[tid] = (tid < 55) ? sql[tid / 11] + klb[tid % 11] : -1e30f;
    __syncthreads();
    if (tid < 32) {
        float mx = fmaxf(lbuf[tid], lbuf[tid + 32]);
        for (int o = 16; o > 0; o >>= 1)
            mx = fmaxf(mx, __shfl_xor_sync(0xffffffffu, mx, o));
        if (tid == 0) red[0] = mx;
    }
    __syncthreads();
    if (tid < 64) {
        float e = (tid < 55) ? expf(lbuf[tid] - red[0]) : 0.f;
        lbuf[tid] = e;
        gbuf[tid] = (tid < 55) ? gbuf[tid] * e : 0.f;
    }
    __syncthreads();
    if (tid < 32) {
        float se = lbuf[tid] + lbuf[tid + 32];
        float sp = gbuf[tid] + gbuf[tid + 32];
        for (int o = 16; o > 0; o >>= 1) {
            se += __shfl_xor_sync(0xffffffffu, se, o);
            sp += __shfl_xor_sync(0xffffffffu, sp, o);
        }
        if (tid == 0) out[b * TT + t + 1] = 1.f / (1.f + expf(-sp / se));
    }
}

// ---------------- launch ----------------
extern "C" void kernel_launch(void* const* d_in, const int* in_sizes, int n_in,
                              void* d_out, int out_size) {
    const int* user      = (const int*)d_in[0];
    const int* question  = (const int*)d_in[1];
    const int* response  = (const int*)d_in[2];
    const int* mask      = (const int*)d_in[3];
    const int* q_nb      = (const int*)d_in[4];
    const int* s_nb      = (const int*)d_in[5];
    const int* u_nb      = (const int*)d_in[6];
    const int* q_nb2     = (const int*)d_in[7];
    const int* qs_index  = (const int*)d_in[8];
    const float* emb_q   = (const float*)d_in[9];
    const float* emb_q2  = (const float*)d_in[10];
    const float* emb_s   = (const float*)d_in[11];
    const float* emb_u   = (const float*)d_in[12];
    const float* emb_r   = (const float*)d_in[13];
    const float* w1      = (const float*)d_in[14];
    const float* w2      = (const float*)d_in[15];
    const float* W_ih    = (const float*)d_in[16];
    const float* W_hh    = (const float*)d_in[17];
    const float* b_ih    = (const float*)d_in[18];
    const float* b_hh    = (const float*)d_in[19];
    const float* agg_w   = (const float*)d_in[20];
    const float* agg_b   = (const float*)d_in[21];
    const float* W_al    = (const float*)d_in[22];
    const float* b_al    = (const float*)d_in[23];
    const float* W_query = (const float*)d_in[24];
    const float* b_query = (const float*)d_in[25];
    const float* W_key   = (const float*)d_in[26];
    const float* b_key   = (const float*)d_in[27];
    const float* W_w     = (const float*)d_in[28];
    const float* b_w     = (const float*)d_in[29];
    const float* W_fus   = (const float*)d_in[30];
    const float* b_fus   = (const float*)d_in[31];
    float* out = (float*)d_out;

    const size_t agg_sm = (5800 + 260) * 4 + 208;    // 24448 B
    cudaFuncSetAttribute(agg_kernel, cudaFuncAttributeMaxDynamicSharedMemorySize, (int)agg_sm);

    setup_kernel<<<12, 256>>>(W_query, b_query, W_key, b_key, W_w, emb_r, W_fus,
                              b_fus, agg_w, W_ih);
    agg_kernel<<<dim3(TS, TB, 2), 256, agg_sm>>>(user, question, mask, q_nb, s_nb,
                                                 u_nb, q_nb2, emb_q, emb_q2, emb_s,
                                                 emb_u, agg_w, agg_b, W_al, b_al);
    fusion_gates_kernel<<<dim3(13, TB), 256>>>(response, w1, w2, b_ih, b_hh);
    scan_kernel<<<TB, 800>>>(mask, W_hh, out);   // profiled slot #4
    attn_kernel<<<dim3(TS, TB), 128>>>(question, qs_index, emb_q, emb_s, b_w, out);
}

// round 15
// speedup vs baseline: 1.0483x; 1.0483x over previous
#include <cuda_runtime.h>

#define TB 32
#define TT 50
#define TS 49
#define DD 100
#define NBR 6
#define SPQ 4
#define RK 10

// ---------------- device scratch ----------------
__device__ __align__(16) float g_eagg[2][TB][TS][DD];
__device__ __align__(16) float g_gates[TB][TS][4 * DD];
__device__ __align__(16) float g_h[TB][TS][DD];
__device__ __align__(16) float g_vq[DD], g_vk[DD];
__device__ __align__(16) float g_resp[2][DD];
__device__ __align__(16) float g_w1t[10000];   // W1^T : [k*100+d]
__device__ __align__(16) float g_w2t[10000];   // W2^T
__device__ __align__(16) float g_wfT[10000];   // W_fusion(:,0:100)^T : [k*100+d]
__device__ __align__(16) float g_wihT[40000];  // W_ih^T : [k*400+j]
__device__ __align__(16) float g_whhP[40000];  // W_hh pair-permuted: [k*800 + tid]
__device__ float g_cq, g_ck;

#define FMA4(ac, a, w) { ac.x += (a) * (w).x; ac.y += (a) * (w).y; ac.z += (a) * (w).z; ac.w += (a) * (w).w; }

__device__ __forceinline__ float tanha(float x) {
    float y;
    asm("tanh.approx.f32 %0, %1;" : "=f"(y) : "f"(x));
    return y;
}

// ---------------- A: precompute + transpose (grid 13) ----------------
__global__ void setup_kernel(const float* __restrict__ W_query,
                             const float* __restrict__ b_query,
                             const float* __restrict__ W_key,
                             const float* __restrict__ b_key,
                             const float* __restrict__ W_w,
                             const float* __restrict__ emb_r,
                             const float* __restrict__ W_fusion,
                             const float* __restrict__ b_fusion,
                             const float* __restrict__ agg_w,
                             const float* __restrict__ W_ih,
                             const float* __restrict__ W_hh) {
    int blk = blockIdx.x, tid = threadIdx.x;
    if (blk == 0) {
        for (int k = tid; k < DD; k += 256) {
            float a = 0.f;
            for (int d = 0; d < DD; d++) a += W_query[d * DD + k] * W_w[d];
            g_vq[k] = a;
        }
        if (tid == 0) {
            float c = 0.f;
            for (int d = 0; d < DD; d++) c += b_query[d] * W_w[d];
            g_cq = c;
        }
    } else if (blk == 1) {
        for (int k = tid; k < DD; k += 256) {
            float a = 0.f;
            for (int d = 0; d < DD; d++) a += W_key[d * DD + k] * W_w[DD + d];
            g_vk[k] = a;
        }
        if (tid == 0) {
            float c = 0.f;
            for (int d = 0; d < DD; d++) c += b_key[d] * W_w[DD + d];
            g_ck = c;
        }
    } else if (blk <= 3) {
        int r = blk - 2;
        for (int d = tid; d < DD; d += 256) {
            float a = b_fusion[d];
            for (int k = 0; k < DD; k++)
                a += emb_r[r * DD + k] * W_fusion[d * 2 * DD + DD + k];
            g_resp[r][d] = a;
        }
    } else if (blk == 4) {
        for (int i = tid; i < 10000; i += 256) {
            int d = i / 100, k = i % 100;
            g_w1t[k * 100 + d] = agg_w[10000 + i];
        }
    } else if (blk == 5) {
        for (int i = tid; i < 10000; i += 256) {
            int d = i / 100, k = i % 100;
            g_w2t[k * 100 + d] = agg_w[20000 + i];
        }
    } else if (blk == 6) {
        for (int i = tid; i < 10000; i += 256) {
            int d = i / 100, k = i % 100;
            g_wfT[k * 100 + d] = W_fusion[d * 200 + k];
        }
    } else if (blk <= 11) {  // blk 7..11: W_ih^T, 8000 each
        int base = (blk - 7) * 8000;
        for (int i = base + tid; i < base + 8000; i += 256) {
            int j = i / 100, k = i - j * 100;
            g_wihT[k * 400 + j] = W_ih[i];
        }
    } else {  // blk 12: W_hh pair-permuted
        for (int i = tid; i < 40000; i += 256) {
            int k = i / 800, t2 = i - k * 800;
            g_whhP[i] = W_hh[(t2 >> 1) * 100 + (t2 & 1) * 50 + k];
        }
    }
}

// warp-cooperative 100x100 matvec (weights from global, coalesced rows)
__device__ __forceinline__ void mv100(const float* __restrict__ in,
                                      const float* __restrict__ Wg,
                                      const float* __restrict__ bg,
                                      float* out, int tid) {
    int w = tid >> 5, l = tid & 31;
    for (int d = w; d < 100; d += 8) {
        float p = 0.f;
        for (int k = l; k < 100; k += 32) p += in[k] * Wg[d * 100 + k];
        for (int o = 16; o > 0; o >>= 1) p += __shfl_xor_sync(0xffffffffu, p, o);
        if (l == 0) out[d] = tanha(p + bg[d]);
    }
}

// 6x100 matmul, 2x2 reg tiles (float2 weights), 150 threads
__device__ __forceinline__ void mm6(const float* __restrict__ in,
                                    const float* __restrict__ W1T,
                                    const float* __restrict__ b1g,
                                    float* out, int tid) {
    if (tid < 150) {
        int r0 = (tid / 50) * 2, d0 = (tid % 50) * 2;
        float a00 = 0.f, a01 = 0.f, a10 = 0.f, a11 = 0.f;
#pragma unroll 4
        for (int k = 0; k < 100; k++) {
            float2 w = *(const float2*)&W1T[k * 100 + d0];
            float x0 = in[r0 * 100 + k], x1 = in[r0 * 100 + 100 + k];
            a00 += x0 * w.x; a01 += x0 * w.y;
            a10 += x1 * w.x; a11 += x1 * w.y;
        }
        float b0 = b1g[d0], b1 = b1g[d0 + 1];
        out[r0 * 100 + d0] = tanha(a00 + b0);
        out[r0 * 100 + d0 + 1] = tanha(a01 + b1);
        out[r0 * 100 + 100 + d0] = tanha(a10 + b0);
        out[r0 * 100 + 100 + d0 + 1] = tanha(a11 + b1);
    }
}

// ---------------- B: graph aggregation ----------------
__global__ __launch_bounds__(256, 6) void agg_kernel(
    const int* __restrict__ user, const int* __restrict__ question,
    const int* __restrict__ mask,
    const int* __restrict__ q_nb, const int* __restrict__ s_nb,
    const int* __restrict__ u_nb, const int* __restrict__ q_nb2,
    const float* __restrict__ emb_q, const float* __restrict__ emb_q2,
    const float* __restrict__ emb_s, const float* __restrict__ emb_u,
    const float* __restrict__ agg_w, const float* __restrict__ agg_b,
    const float* __restrict__ W_last, const float* __restrict__ b_last) {
    int t = blockIdx.x, b = blockIdx.y, side = blockIdx.z, tid = threadIdx.x;
    int qt = question[b * TT + t];
    float* outg = &g_eagg[side][b][t][0];
    if (mask[b * TT + t] == 0) {
        const float* src = side ? emb_q2 + (size_t)qt * DD : emb_q + (size_t)qt * DD;
        for (int d = tid; d < DD; d += 256) outg[d] = src[d];
        return;
    }
    extern __shared__ float sm[];
    float* e2s = sm;            // 3600
    float* e1  = e2s + 3600;    // 600
    float* e1b = e1 + 600;      // 600
    float* s6  = e1b + 600;     // 600
    float* e0v = s6 + 600;      // 100
    float* e0b = e0v + 100;     // 100
    float* e0c = e0b + 100;     // 100
    float* s1  = e0c + 100;     // 100  -> 5800 floats
    int* sn1 = (int*)(s1 + 100);  // 8
    int* sn2 = sn1 + 8;           // 36
    int* sn3 = sn2 + 36;          // 216 -> 260 ints

    int n0 = side ? user[b * TT + t] : qt;
    const int* tA = side ? u_nb : q_nb;
    const int* tB = side ? q_nb2 : s_nb;
    const float* eE = side ? emb_u : emb_q;
    const float* eO = side ? emb_q2 : emb_s;
    const float* b0g = agg_b;
    const float* b1g = agg_b + DD;
    const float* b2g = agg_b + 2 * DD;
    const float* W0g = agg_w;

    int g0 = tid / 100;
    int d0i = tid - g0 * 100;

    if (tid < NBR) sn1[tid] = tA[n0 * NBR + tid];
    for (int d = tid; d < 100; d += 256) e0v[d] = eE[(size_t)n0 * DD + d];
    __syncthreads();
    if (tid < 36) sn2[tid] = tB[sn1[tid / 6] * NBR + tid % 6];
    for (int i = tid; i < 600; i += 256)
        e1[i] = eO[(size_t)sn1[i / 100] * DD + i % 100];
    __syncthreads();
    if (tid < 216) sn3[tid] = tA[sn2[tid / 6] * NBR + tid % 6];
    {
        int g = g0, d = d0i;
        for (int i = tid; i < 3600; i += 256) {
            e2s[i] = eE[(size_t)sn2[g] * DD + d];
            d += 56; g += 2;
            if (d >= 100) { d -= 100; ++g; }
        }
    }
    __syncthreads();
    for (int i = tid; i < 600; i += 256) {
        int r = i / 100, d = i % 100;
        float s = 0.f;
        for (int r2 = 0; r2 < 6; r2++) s += e2s[(r * 6 + r2) * 100 + d];
        s6[i] = s * (1.f / 6.f) + e1[i];
    }
    if (tid < 100) {
        float s = 0.f;
        for (int r = 0; r < 6; r++) s += e1[r * 100 + tid];
        s1[tid] = s * (1.f / 6.f) + e0v[tid];
    }
    __syncthreads();
    mv100(s1, W0g, b0g, e0b, tid);  // i=0 j=0
    {
        int g = g0, d = d0i;
        for (int i = tid; i < 3600; i += 256) {
            const int* s3 = sn3 + g * 6;
            float s = eO[(size_t)s3[0] * DD + d] + eO[(size_t)s3[1] * DD + d] +
                      eO[(size_t)s3[2] * DD + d] + eO[(size_t)s3[3] * DD + d] +
                      eO[(size_t)s3[4] * DD + d] + eO[(size_t)s3[5] * DD + d];
            e2s[i] += s * (1.f / 6.f);
            d += 56; g += 2;
            if (d >= 100) { d -= 100; ++g; }
        }
    }
    __syncthreads();
    // i=0 j=2 : 36x100 @ W2^T, 4x4 reg tiles, in-place
    float4 ac0, ac1, ac2, ac3;
    int r0 = 0, c0 = 0;
    if (tid < 225) {
        r0 = (tid / 25) * 4; c0 = (tid % 25) * 4;
        ac0 = make_float4(0, 0, 0, 0); ac1 = ac0; ac2 = ac0; ac3 = ac0;
#pragma unroll 2
        for (int k = 0; k < 100; k++) {
            float4 w = *(const float4*)&g_w2t[k * 100 + c0];
            float x0 = e2s[r0 * 100 + k];
            float x1 = e2s[r0 * 100 + 100 + k];
            float x2 = e2s[r0 * 100 + 200 + k];
            float x3 = e2s[r0 * 100 + 300 + k];
            FMA4(ac0, x0, w); FMA4(ac1, x1, w); FMA4(ac2, x2, w); FMA4(ac3, x3, w);
        }
    }
    __syncthreads();
    if (tid < 225) {
        float bb0 = b2g[c0], bb1 = b2g[c0 + 1], bb2 = b2g[c0 + 2], bb3 = b2g[c0 + 3];
        float* o0 = e2s + r0 * 100 + c0;
        o0[0] = tanha(ac0.x + bb0); o0[1] = tanha(ac0.y + bb1); o0[2] = tanha(ac0.z + bb2); o0[3] = tanha(ac0.w + bb3);
        o0[100] = tanha(ac1.x + bb0); o0[101] = tanha(ac1.y + bb1); o0[102] = tanha(ac1.z + bb2); o0[103] = tanha(ac1.w + bb3);
        o0[200] = tanha(ac2.x + bb0); o0[201] = tanha(ac2.y + bb1); o0[202] = tanha(ac2.z + bb2); o0[203] = tanha(ac2.w + bb3);
        o0[300] = tanha(ac3.x + bb0); o0[301] = tanha(ac3.y + bb1); o0[302] = tanha(ac3.z + bb2); o0[303] = tanha(ac3.w + bb3);
    }
    mm6(s6, g_w1t, b1g, e1b, tid);  // i=0 j=1
    __syncthreads();
    for (int i = tid; i < 600; i += 256) {
        int r = i / 100, d = i % 100;
        float s = 0.f;
        for (int r2 = 0; r2 < 6; r2++) s += e2s[(r * 6 + r2) * 100 + d];
        s6[i] = s * (1.f / 6.f) + e1b[i];
    }
    if (tid < 100) {
        float s = 0.f;
        for (int r = 0; r < 6; r++) s += e1b[r * 100 + tid];
        s1[tid] = s * (1.f / 6.f) + e0b[tid];
    }
    __syncthreads();
    mv100(s1, W0g, b0g, e0c, tid);  // i=1 j=0
    mm6(s6, g_w1t, b1g, e1, tid);   // i=1 j=1
    __syncthreads();
    if (tid < 100) {
        float s = 0.f;
        for (int r = 0; r < 6; r++) s += e1[r * 100 + tid];
        s1[tid] = s * (1.f / 6.f) + e0c[tid];
    }
    __syncthreads();
    mv100(s1, W0g, b0g, e0v, tid);  // i=2 j=0
    __syncthreads();
    mv100(e0v, W_last, b_last, outg, tid);  // final
}

// ---------------- C: fused fusion + input gates ----------------
__global__ __launch_bounds__(256) void fusion_gates_kernel(
    const int* __restrict__ response, const float* __restrict__ w1p,
    const float* __restrict__ w2p, const float* __restrict__ b_ih,
    const float* __restrict__ b_hh) {
    int tc = blockIdx.x, b = blockIdx.y, tid = threadIdx.x;
    int t0 = tc * 4;
    __shared__ float eh[400], et[400];
    float w1 = *w1p, w2 = *w2p;
    for (int i = tid; i < 400; i += 256) {
        int t = t0 + i / 100, d = i % 100;
        eh[i] = (t < TS) ? w1 * g_eagg[0][b][t][d] + w2 * g_eagg[1][b][t][d] : 0.f;
    }
    __syncthreads();
    if (tid < 100) {
        int tt = tid / 25, d0 = (tid % 25) * 4;
        int t = t0 + tt;
        if (t < TS) {
            float4 ac = make_float4(0, 0, 0, 0);
            const float* x = eh + tt * 100;
#pragma unroll 4
            for (int k = 0; k < 100; k++) {
                float4 w = *(const float4*)&g_wfT[k * 100 + d0];
                FMA4(ac, x[k], w);
            }
            int r = response[b * TT + t];
            et[tt * 100 + d0]     = fmaxf(ac.x + g_resp[r][d0], 0.f);
            et[tt * 100 + d0 + 1] = fmaxf(ac.y + g_resp[r][d0 + 1], 0.f);
            et[tt * 100 + d0 + 2] = fmaxf(ac.z + g_resp[r][d0 + 2], 0.f);
            et[tt * 100 + d0 + 3] = fmaxf(ac.w + g_resp[r][d0 + 3], 0.f);
        }
    }
    __syncthreads();
    for (int u = tid; u < 400; u += 256) {
        int tt = u / 100, j0 = (u % 100) * 4;
        int t = t0 + tt;
        if (t < TS) {
            float4 ac = make_float4(0, 0, 0, 0);
            const float* x = et + tt * 100;
#pragma unroll 4
            for (int k = 0; k < 100; k++) {
                float4 w = *(const float4*)&g_wihT[k * 400 + j0];
                FMA4(ac, x[k], w);
            }
            g_gates[b][t][j0]     = ac.x + b_ih[j0] + b_hh[j0];
            g_gates[b][t][j0 + 1] = ac.y + b_ih[j0 + 1] + b_hh[j0 + 1];
            g_gates[b][t][j0 + 2] = ac.z + b_ih[j0 + 2] + b_hh[j0 + 2];
            g_gates[b][t][j0 + 3] = ac.w + b_ih[j0 + 3] + b_hh[j0 + 3];
        }
    }
}

// ---------------- D: LSTM scan — pair-split regs + coalesced W + fast act ----------------
__global__ __launch_bounds__(800, 1) void scan_kernel(
    const int* __restrict__ mask, float* __restrict__ out) {
    int b = blockIdx.x, tid = threadIdx.x;
    __shared__ __align__(16) float h[100];
    __shared__ float c[100], gs[400];
    __shared__ int mlist[TS + 1];
    __shared__ int snm;
    int j = tid >> 1, half = tid & 1;   // thread pair (2j, 2j+1) owns row j
    float w[50];
#pragma unroll
    for (int k = 0; k < 50; k++) w[k] = g_whhP[k * 800 + tid];  // coalesced
    if (tid < 100) { h[tid] = 0.f; c[tid] = 0.f; }
    if (tid == 0) {
        out[b * TT] = 0.5f;
        int n = 0;
        for (int t = 0; t < TS; t++)
            if (mask[b * TT + t]) mlist[n++] = t;
        mlist[n] = TS;
        snm = n;
    }
    __syncthreads();
    int nm = snm;
    int first = (nm > 0) ? mlist[0] : TS;
    if (tid < 100)
        for (int t = 0; t < first; t++) g_h[b][t][tid] = 0.f;
    float ginc = (nm > 0 && half == 0) ? g_gates[b][mlist[0]][j] : 0.f;
    const float* hh = h + half * 50;
    for (int idx = 0; idx < nm; idx++) {
        int tm = mlist[idx], tn = mlist[idx + 1];
        {
            float a0 = 0.f, a1 = 0.f;
#pragma unroll
            for (int k = 0; k < 48; k += 4) {   // k = 0,4,...,44 covers hh[0..47]
                float2 h0 = *(const float2*)&hh[k];
                float2 h1 = *(const float2*)&hh[k + 2];
                a0 += h0.x * w[k]     + h0.y * w[k + 1];
                a1 += h1.x * w[k + 2] + h1.y * w[k + 3];
            }
            float2 ht = *(const float2*)&hh[48];   // tail 48,49
            a0 += ht.x * w[48] + ht.y * w[49];
            float p = a0 + a1;
            p += __shfl_xor_sync(0xffffffffu, p, 1);   // pair combine
            if (half == 0) gs[j] = p + ginc;
        }
        if (idx + 1 < nm && half == 0) ginc = g_gates[b][mlist[idx + 1]][j];
        __syncthreads();
        if (tid < 100) {
            float gi = gs[tid], gf = gs[100 + tid], gg = gs[200 + tid], go = gs[300 + tid];
            float si = 0.5f + 0.5f * tanha(0.5f * gi);
            float sf = 0.5f + 0.5f * tanha(0.5f * gf);
            float so = 0.5f + 0.5f * tanha(0.5f * go);
            float c2 = sf * c[tid] + si * tanha(gg);
            float h2 = so * tanha(c2);
            h[tid] = h2; c[tid] = c2;
            for (int t = tm; t < tn; t++) g_h[b][t][tid] = h2;
        }
        __syncthreads();
    }
}

// ---------------- E: prep + attention fused, grid (TS, TB) ----------------
__global__ __launch_bounds__(128) void attn_kernel(
    const int* __restrict__ question, const int* __restrict__ qs_index,
    const float* __restrict__ emb_q, const float* __restrict__ emb_s,
    const float* __restrict__ b_w, float* __restrict__ out) {
    int t = blockIdx.x, b = blockIdx.y, tid = threadIdx.x;
    __shared__ float st[1100], qsm[500], vks[100], sc[52], lbuf[64], gbuf[64],
                     klb[16], red[2], sql[5];
    __shared__ int sidx[10], ssv[10];
    int qn = question[b * TT + t + 1];
    for (int i = tid; i < 500; i += 128) {
        int q = i / 100, d = i % 100;
        qsm[i] = (q == 0) ? emb_q[(size_t)qn * DD + d]
                          : emb_s[(size_t)qs_index[qn * SPQ + q - 1] * DD + d];
    }
    for (int d = tid; d < 100; d += 128) vks[d] = g_vk[d];
    __syncthreads();
    if (tid < 5) {
        float a = g_cq;
        for (int d = 0; d < 100; d++) a += qsm[tid * 100 + d] * g_vq[d];
        sql[tid] = a;
    }
    for (int i = tid; i < t; i += 128) {
        const float* er = emb_q + (size_t)question[b * TT + i] * DD;
        float a = 0.f;
#pragma unroll 4
        for (int d = 0; d < 100; d++) a += er[d] * qsm[d];
        sc[i] = a;
    }
    __syncthreads();
    if (tid == 0) {  // exact stable top-k over i < t
        unsigned long long used = 0ULL;
        for (int s = 0; s < RK; s++) {
            float best = -1e38f; int bi = -1;
            for (int i = 0; i < t; i++)
                if (!((used >> i) & 1ULL) && sc[i] > best) { best = sc[i]; bi = i; }
            if (bi >= 0) { sidx[s] = bi; ssv[s] = 1; used |= 1ULL << bi; }
            else         { sidx[s] = 0;  ssv[s] = 0; }
        }
    }
    __syncthreads();
    for (int i = tid; i < 1100; i += 128) {
        int s = i / 100, d = i % 100;
        int row = (s == 0) ? t : sidx[s - 1];
        st[i] = g_h[b][row][d];
    }
    __syncthreads();
    float ckb = g_ck + b_w[0];
    if (tid < 55) {
        int q = tid / 11, s = tid % 11;
        bool v = (s == 0) || ssv[s - 1];
        float a = 0.f;
        if (v) {
            const float* qr = qsm + q * 100;
            const float* sr = st + s * 100;
#pragma unroll 4
            for (int d = 0; d < 100; d++) a += qr[d] * sr[d];
        }
        gbuf[tid] = a;
    } else if (tid < 66) {
        int s = tid - 55;
        bool v = (s == 0) || ssv[s - 1];
        float a = -1e30f;
        if (v) {
            a = ckb;
            const float* sr = st + s * 100;
#pragma unroll 4
            for (int d = 0; d < 100; d++) a += sr[d] * vks[d];
        }
        klb[s] = a;
    }
    __syncthreads();
    if (tid < 64) lbuf[tid] = (tid < 55) ? sql[tid / 11] + klb[tid % 11] : -1e30f;
    __syncthreads();
    if (tid < 32) {
        float mx = fmaxf(lbuf[tid], lbuf[tid + 32]);
        for (int o = 16; o > 0; o >>= 1)
            mx = fmaxf(mx, __shfl_xor_sync(0xffffffffu, mx, o));
        if (tid == 0) red[0] = mx;
    }
    __syncthreads();
    if (tid < 64) {
        float e = (tid < 55) ? expf(lbuf[tid] - red[0]) : 0.f;
        lbuf[tid] = e;
        gbuf[tid] = (tid < 55) ? gbuf[tid] * e : 0.f;
    }
    __syncthreads();
    if (tid < 32) {
        float se = lbuf[tid] + lbuf[tid + 32];
        float sp = gbuf[tid] + gbuf[tid + 32];
        for (int o = 16; o > 0; o >>= 1) {
            se += __shfl_xor_sync(0xffffffffu, se, o);
            sp += __shfl_xor_sync(0xffffffffu, sp, o);
        }
        if (tid == 0) out[b * TT + t + 1] = 1.f / (1.f + expf(-sp / se));
    }
}

// ---------------- launch ----------------
extern "C" void kernel_launch(void* const* d_in, const int* in_sizes, int n_in,
                              void* d_out, int out_size) {
    const int* user      = (const int*)d_in[0];
    const int* question  = (const int*)d_in[1];
    const int* response  = (const int*)d_in[2];
    const int* mask      = (const int*)d_in[3];
    const int* q_nb      = (const int*)d_in[4];
    const int* s_nb      = (const int*)d_in[5];
    const int* u_nb      = (const int*)d_in[6];
    const int* q_nb2     = (const int*)d_in[7];
    const int* qs_index  = (const int*)d_in[8];
    const float* emb_q   = (const float*)d_in[9];
    const float* emb_q2  = (const float*)d_in[10];
    const float* emb_s   = (const float*)d_in[11];
    const float* emb_u   = (const float*)d_in[12];
    const float* emb_r   = (const float*)d_in[13];
    const float* w1      = (const float*)d_in[14];
    const float* w2      = (const float*)d_in[15];
    const float* W_ih    = (const float*)d_in[16];
    const float* W_hh    = (const float*)d_in[17];
    const float* b_ih    = (const float*)d_in[18];
    const float* b_hh    = (const float*)d_in[19];
    const float* agg_w   = (const float*)d_in[20];
    const float* agg_b   = (const float*)d_in[21];
    const float* W_al    = (const float*)d_in[22];
    const float* b_al    = (const float*)d_in[23];
    const float* W_query = (const float*)d_in[24];
    const float* b_query = (const float*)d_in[25];
    const float* W_key   = (const float*)d_in[26];
    const float* b_key   = (const float*)d_in[27];
    const float* W_w     = (const float*)d_in[28];
    const float* b_w     = (const float*)d_in[29];
    const float* W_fus   = (const float*)d_in[30];
    const float* b_fus   = (const float*)d_in[31];
    float* out = (float*)d_out;

    const size_t agg_sm = (5800 + 260) * 4 + 208;    // 24448 B
    cudaFuncSetAttribute(agg_kernel, cudaFuncAttributeMaxDynamicSharedMemorySize, (int)agg_sm);

    setup_kernel<<<13, 256>>>(W_query, b_query, W_key, b_key, W_w, emb_r, W_fus,
                              b_fus, agg_w, W_ih, W_hh);
    agg_kernel<<<dim3(TS, TB, 2), 256, agg_sm>>>(user, question, mask, q_nb, s_nb,
                                                 u_nb, q_nb2, emb_q, emb_q2, emb_s,
                                                 emb_u, agg_w, agg_b, W_al, b_al);
    fusion_gates_kernel<<<dim3(13, TB), 256>>>(response, w1, w2, b_ih, b_hh);
    scan_kernel<<<TB, 800>>>(mask, out);   // profiled slot #4
    attn_kernel<<<dim3(TS, TB), 128>>>(question, qs_index, emb_q, emb_s, b_w, out);
}